// round 15
// baseline (speedup 1.0000x reference)
#include <cuda_runtime.h>
#include <cuda_bf16.h>
#include <cstdint>

// ---------------------------------------------------------------------------
// GIN via mma.sync.m16n8k16.bf16 double-bf16 split (3-product ~fp32):
//   a = a0 + a1 (bf16 each);  D += a0b0 + a0b1 + a1b0  (err ~2^-17/product)
// GEMM: cp.async.cg double-buffered, 2 CTAs/SM, 8 warps (2m x 4n), BK=32,
// scalar-LDS fragment loads. M-tile templated: MT=4 -> 128 rows (N=256
// GEMMs), MT=3 -> 96 rows (N<=128 GEMMs: kills wave-quantization tail).
// CSR exclusive scan fused into ONE kernel (last-arriving-block pattern).
// ---------------------------------------------------------------------------

#define MAXN 50000
#define MAXE 1000000

__device__ __align__(16) unsigned g_P0[MAXN * 128];
__device__ __align__(16) unsigned g_P1[MAXN * 128];
__device__ __align__(16) unsigned g_Q0[MAXN * 128];
__device__ __align__(16) unsigned g_Q1[MAXN * 128];
__device__ __align__(16) float    g_hf[MAXN * 128];   // fp32 h1 (gather2 input)
__device__ __align__(16) unsigned g_W0[81920];        // all split weights, plane 0
__device__ __align__(16) unsigned g_W1[81920];        // plane 1
__device__ int g_rowptr[MAXN + 1];
__device__ int g_cursor[MAXN];
__device__ int g_deg   [MAXN];
__device__ int g_srcs  [MAXE];
__device__ int g_src32 [MAXE];
__device__ int g_dst32 [MAXE];
__device__ int g_aggr  [256];
__device__ int g_arrive;
__device__ int g_scan_flag;

// weight segment offsets (u32 elements within g_W0/g_W1)
#define OFF_W1 0
#define OFF_W2 8192
#define OFF_W3 16384
#define OFF_W4 32768
#define OFF_WL 65536

__device__ __forceinline__ const unsigned* planeR(int sel, int p) {
    if (sel == 0) return p ? g_P1 : g_P0;
    return p ? g_Q1 : g_Q0;
}
__device__ __forceinline__ unsigned* planeW(int sel, int p) {
    if (sel == 0) return p ? g_P1 : g_P0;
    return p ? g_Q1 : g_Q0;
}

__device__ __forceinline__ void split2(float e, float o,
                                       unsigned& hi, unsigned& lo) {
    __nv_bfloat16 he = __float2bfloat16_rn(e);
    __nv_bfloat16 ho = __float2bfloat16_rn(o);
    float re = e - __bfloat162float(he);
    float ro = o - __bfloat162float(ho);
    __nv_bfloat16 rhe = __float2bfloat16_rn(re);
    __nv_bfloat16 rho = __float2bfloat16_rn(ro);
    hi = ((unsigned)__bfloat16_as_ushort(ho) << 16) | __bfloat16_as_ushort(he);
    lo = ((unsigned)__bfloat16_as_ushort(rho) << 16) | __bfloat16_as_ushort(rhe);
}

#define MMA_BF16(d, a, b)                                                     \
    asm volatile(                                                             \
        "mma.sync.aligned.m16n8k16.row.col.f32.bf16.bf16.f32 "               \
        "{%0,%1,%2,%3},{%4,%5,%6,%7},{%8,%9},{%0,%1,%2,%3};"                 \
        : "+f"((d)[0]), "+f"((d)[1]), "+f"((d)[2]), "+f"((d)[3])             \
        : "r"((a)[0]), "r"((a)[1]), "r"((a)[2]), "r"((a)[3]),                \
          "r"((b)[0]), "r"((b)[1]))

// 16B cp.async with zero-fill when pred is false (src-size=0 form)
__device__ __forceinline__ void cp16(uint32_t dst, const void* src, bool pred) {
    int sz = pred ? 16 : 0;
    asm volatile("cp.async.cg.shared.global [%0], [%1], 16, %2;"
                 :: "r"(dst), "l"(src), "r"(sz) : "memory");
}
#define CP_COMMIT() asm volatile("cp.async.commit_group;" ::: "memory")
#define CP_WAIT(n)  asm volatile("cp.async.wait_group %0;" :: "n"(n) : "memory")

// =========== fused: weight split for ALL GEMMs + deg zero + scan reset ======
__global__ void prep_all(const float* __restrict__ W1, const float* __restrict__ W2,
                         const float* __restrict__ W3, const float* __restrict__ W4,
                         const float* __restrict__ Wl, int N) {
    int idx = blockIdx.x * blockDim.x + threadIdx.x;
    if (idx == 0) { g_arrive = 0; g_scan_flag = 0; }
    if (idx < N) g_deg[idx] = 0;
    if (idx >= 81920) return;
    const float* W; int off, NW, N_real;
    if      (idx < OFF_W2) { W = W1; off = OFF_W1; NW = 128; N_real = 128; }
    else if (idx < OFF_W3) { W = W2; off = OFF_W2; NW = 128; N_real = 128; }
    else if (idx < OFF_W4) { W = W3; off = OFF_W3; NW = 256; N_real = 256; }
    else if (idx < OFF_WL) { W = W4; off = OFF_W4; NW = 256; N_real = 256; }
    else                   { W = Wl; off = OFF_WL; NW = 128; N_real = 40;  }
    int rel = idx - off;
    int kp = rel / NW, n = rel % NW;
    float e = 0.f, o = 0.f;
    if (n < N_real) {
        e = W[(size_t)(2 * kp) * N_real + n];
        o = W[(size_t)(2 * kp + 1) * N_real + n];
    }
    unsigned hi, lo;
    split2(e, o, hi, lo);
    g_W0[idx] = hi;
    g_W1[idx] = lo;
}

// =========== fused: dtype detect + index convert + degree histogram =========
__global__ void convert_hist(const unsigned int* __restrict__ w, int E, int N) {
    __shared__ int s_is64;
    if (threadIdx.x < 32) {
        unsigned int o = 0;
        for (int i = 1 + 2 * (int)threadIdx.x; i < 256; i += 64) o |= w[i];
        #pragma unroll
        for (int k = 16; k > 0; k >>= 1)
            o |= __shfl_down_sync(0xffffffffu, o, k);
        if (threadIdx.x == 0) s_is64 = (o == 0) ? 1 : 0;
    }
    __syncthreads();
    const int is64 = s_is64;
    const int e = blockIdx.x * blockDim.x + threadIdx.x;
    if (e >= E) return;
    int s, d;
    if (is64) { s = (int)w[2 * e]; d = (int)w[2 * (E + e)]; }
    else      { s = (int)w[e];     d = (int)w[E + e]; }
    s = min(max(s, 0), N - 1);
    d = min(max(d, 0), N - 1);
    g_src32[e] = s;
    g_dst32[e] = d;
    atomicAdd(&g_deg[d], 1);
}

// =========== single-launch exclusive scan (last-arriving-block) =============
// All blocks resident (nB <= 256 << slots). Block scans its 256 degs, keeps
// per-thread exclusive value in a register, publishes aggregate; last block
// to arrive scans the aggregates and raises the flag; all add their base.
__global__ void scan_fused(int N, int E, int nB) {
    __shared__ int s[256];
    __shared__ int rank;
    const int t = threadIdx.x, b = blockIdx.x;
    const int i = b * 256 + t;
    const int v = (i < N) ? g_deg[i] : 0;
    s[t] = v;
    __syncthreads();
    #pragma unroll
    for (int off = 1; off < 256; off <<= 1) {
        int tmp = (t >= off) ? s[t - off] : 0;
        __syncthreads();
        s[t] += tmp;
        __syncthreads();
    }
    const int myexc = s[t] - v;          // keep: s[] is reused below
    if (t == 255) g_aggr[b] = s[255];
    __threadfence();
    if (t == 0) rank = atomicAdd(&g_arrive, 1);
    __syncthreads();

    if (rank == nB - 1) {                // last arrival: all aggregates visible
        int a = (t < nB) ? *((volatile int*)&g_aggr[t]) : 0;
        __syncthreads();
        s[t] = a;
        __syncthreads();
        #pragma unroll
        for (int off = 1; off < 256; off <<= 1) {
            int tmp = (t >= off) ? s[t - off] : 0;
            __syncthreads();
            s[t] += tmp;
            __syncthreads();
        }
        if (t < nB) g_aggr[t] = s[t] - a;   // exclusive block base
        __threadfence();
        if (t == 0) *((volatile int*)&g_scan_flag) = 1;
    }
    if (t == 0) {
        while (*((volatile int*)&g_scan_flag) == 0) { }
    }
    __syncthreads();
    __threadfence();
    const int base = *((volatile int*)&g_aggr[b]);
    if (i < N) {
        int r = base + myexc;
        g_rowptr[i] = r;
        g_cursor[i] = r;
    }
    if (i == N) g_rowptr[N] = E;
}

__global__ void fill_csr(int E) {
    int e = blockIdx.x * blockDim.x + threadIdx.x;
    if (e >= E) return;
    int p = atomicAdd(&g_cursor[g_dst32[e]], 1);
    g_srcs[p] = g_src32[e];
}

// ===================== GIN aggregation (split output) =======================
__global__ void gin_aggregate_split(const float* __restrict__ h_ext,
                                    int use_ext, int N) {
    const int warp = (blockIdx.x * blockDim.x + threadIdx.x) >> 5;
    if (warp >= N) return;
    const int lane = threadIdx.x & 31;
    const float* __restrict__ h = use_ext ? h_ext : g_hf;
    const float4* __restrict__ hp = reinterpret_cast<const float4*>(h);
    float4 acc = hp[(size_t)warp * 32 + lane];
    const int beg = g_rowptr[warp];
    const int end = g_rowptr[warp + 1];
    for (int j = beg; j < end; j++) {
        const int s = g_srcs[j];
        const float4 v = hp[(size_t)s * 32 + lane];
        acc.x += v.x; acc.y += v.y; acc.z += v.z; acc.w += v.w;
    }
    unsigned h0, l0, h1, l1;
    split2(acc.x, acc.y, h0, l0);
    split2(acc.z, acc.w, h1, l1);
    const size_t o = (size_t)warp * 32 + lane;
    reinterpret_cast<uint2*>(g_P0)[o] = make_uint2(h0, h1);
    reinterpret_cast<uint2*>(g_P1)[o] = make_uint2(l0, l1);
}

// ======================= bf16x3 GEMM (mma.m16n8k16) =========================
// MT = m-subtiles per warp (block rows = MT*32: 4->128, 3->96).
// NTL = n-subtiles per warp (4 -> 128-col block, 2 -> 64-col head block).
// CMODE: 0 split planes, 1 fp32 g_hf, 2 external fp32 (masked).
template<bool RELU, int CMODE, int NTL, int MT>
__global__ void __launch_bounds__(256, 2)
gemm_bf16(int a_sel, int c_sel, float* __restrict__ c_ext,
          const float* __restrict__ bias, int w_off,
          int M, int N_real, int NW, int K)
{
    extern __shared__ __align__(16) unsigned smem[];
    constexpr int AR   = MT * 32;              // block rows
    constexpr int AP1  = AR * 20;              // A plane1 offset (u32)
    constexpr int BP0  = 2 * AR * 20;          // B plane0
    constexpr int BP1  = BP0 + 16 * 136;       // B plane1
    constexpr int STG  = BP1 + 16 * 136;       // u32 per stage
    constexpr int BCOLS = NTL * 32;            // block column coverage
    const uint32_t smem_b = (uint32_t)__cvta_generic_to_shared(smem);

    const int tid  = threadIdx.x;
    const int wid  = tid >> 5;
    const int lane = tid & 31;
    const int gid  = lane >> 2;
    const int tig  = lane & 3;
    const int wm   = wid >> 2;
    const int wn   = wid & 3;
    const int row0 = blockIdx.y * AR;
    const int col0 = blockIdx.x * BCOLS;

    const unsigned* __restrict__ A0g = planeR(a_sel, 0);
    const unsigned* __restrict__ A1g = planeR(a_sel, 1);
    const unsigned* __restrict__ W0g = g_W0 + w_off;
    const unsigned* __restrict__ W1g = g_W1 + w_off;

    const int a_r = tid >> 1, a_seg = (tid & 1) * 8;
    const int b_kp = tid >> 4, b_c0 = (tid & 15) * 8;
    const bool a_use = (a_r < AR);            // MT=3: top 64 threads skip A
    const int a_gr = row0 + a_r;
    const bool a_ok = a_use && (a_gr < M);
    const bool b_ok = (b_c0 < BCOLS);
    const int Kh = K >> 1;

    float acc[MT][NTL][4];
    #pragma unroll
    for (int mt = 0; mt < MT; mt++)
        #pragma unroll
        for (int nt = 0; nt < NTL; nt++)
            #pragma unroll
            for (int q = 0; q < 4; q++) acc[mt][nt][q] = 0.f;

    auto stage = [&](int ch, int buf) {
        const int kp0 = ch << 4;
        const uint32_t sb = smem_b + (uint32_t)(buf * STG) * 4u;
        if (a_use) {
            const uint32_t a_off = (uint32_t)(a_r * 20 + a_seg) * 4u;
            cp16(sb + a_off,      A0g + (size_t)a_gr * Kh + kp0 + a_seg,     a_ok);
            cp16(sb + a_off + 16, A0g + (size_t)a_gr * Kh + kp0 + a_seg + 4, a_ok);
            cp16(sb + (uint32_t)AP1 * 4u + a_off,      A1g + (size_t)a_gr * Kh + kp0 + a_seg,     a_ok);
            cp16(sb + (uint32_t)AP1 * 4u + a_off + 16, A1g + (size_t)a_gr * Kh + kp0 + a_seg + 4, a_ok);
        }
        const uint32_t b_off = (uint32_t)(b_kp * 136 + b_c0) * 4u;
        const size_t bg = (size_t)(kp0 + b_kp) * NW + col0 + b_c0;
        cp16(sb + (uint32_t)BP0 * 4u + b_off,      W0g + bg,     b_ok);
        cp16(sb + (uint32_t)BP0 * 4u + b_off + 16, W0g + bg + 4, b_ok);
        cp16(sb + (uint32_t)BP1 * 4u + b_off,      W1g + bg,     b_ok);
        cp16(sb + (uint32_t)BP1 * 4u + b_off + 16, W1g + bg + 4, b_ok);
        CP_COMMIT();
    };

    const int nch = K >> 5;
    stage(0, 0);
    for (int ch = 0; ch < nch; ch++) {
        if (ch + 1 < nch) {
            stage(ch + 1, (ch + 1) & 1);
            CP_WAIT(1);
        } else {
            CP_WAIT(0);
        }
        __syncthreads();

        const unsigned* S   = smem + (ch & 1) * STG;
        const unsigned* As0 = S;
        const unsigned* As1 = S + AP1;
        const unsigned* Bs0 = S + BP0;
        const unsigned* Bs1 = S + BP1;

        #pragma unroll
        for (int s = 0; s < 2; s++) {
            const int so = s * 8;
            uint32_t B0f[NTL][2], B1f[NTL][2];
            #pragma unroll
            for (int nt = 0; nt < NTL; nt++) {
                const int c = wn * (NTL * 8) + nt * 8 + gid;
                B0f[nt][0] = Bs0[(so + tig    ) * 136 + c];
                B0f[nt][1] = Bs0[(so + tig + 4) * 136 + c];
                B1f[nt][0] = Bs1[(so + tig    ) * 136 + c];
                B1f[nt][1] = Bs1[(so + tig + 4) * 136 + c];
            }
            #pragma unroll
            for (int mt = 0; mt < MT; mt++) {
                const int r = wm * (MT * 16) + mt * 16 + gid;
                uint32_t A0f[4], A1f[4];
                A0f[0] = As0[(r    ) * 20 + so + tig    ];
                A0f[1] = As0[(r + 8) * 20 + so + tig    ];
                A0f[2] = As0[(r    ) * 20 + so + tig + 4];
                A0f[3] = As0[(r + 8) * 20 + so + tig + 4];
                A1f[0] = As1[(r    ) * 20 + so + tig    ];
                A1f[1] = As1[(r + 8) * 20 + so + tig    ];
                A1f[2] = As1[(r    ) * 20 + so + tig + 4];
                A1f[3] = As1[(r + 8) * 20 + so + tig + 4];
                #pragma unroll
                for (int nt = 0; nt < NTL; nt++)
                    MMA_BF16(acc[mt][nt], A0f, B0f[nt]);   // a0*b0
                #pragma unroll
                for (int nt = 0; nt < NTL; nt++)
                    MMA_BF16(acc[mt][nt], A0f, B1f[nt]);   // a0*b1
                #pragma unroll
                for (int nt = 0; nt < NTL; nt++)
                    MMA_BF16(acc[mt][nt], A1f, B0f[nt]);   // a1*b0
            }
        }
        __syncthreads();
    }

    // ---- epilogue ----
    unsigned* C0 = planeW(c_sel, 0);
    unsigned* C1 = planeW(c_sel, 1);
    #pragma unroll
    for (int mt = 0; mt < MT; mt++) {
        #pragma unroll
        for (int nt = 0; nt < NTL; nt++) {
            const int c = col0 + wn * (NTL * 8) + nt * 8 + 2 * tig;
            #pragma unroll
            for (int half = 0; half < 2; half++) {
                const int r = row0 + wm * (MT * 16) + mt * 16 + gid + half * 8;
                if (r >= M) continue;
                float v0 = acc[mt][nt][half * 2 + 0];
                float v1 = acc[mt][nt][half * 2 + 1];
                if (CMODE == 2) {
                    if (c < N_real) {
                        v0 += __ldg(&bias[c]);
                        if (RELU) v0 = fmaxf(v0, 0.f);
                        c_ext[(size_t)r * N_real + c] = v0;
                    }
                    if (c + 1 < N_real) {
                        v1 += __ldg(&bias[c + 1]);
                        if (RELU) v1 = fmaxf(v1, 0.f);
                        c_ext[(size_t)r * N_real + c + 1] = v1;
                    }
                } else {
                    v0 += __ldg(&bias[c]);
                    v1 += __ldg(&bias[c + 1]);
                    if (RELU) { v0 = fmaxf(v0, 0.f); v1 = fmaxf(v1, 0.f); }
                    if (CMODE == 1) {
                        *reinterpret_cast<float2*>(&g_hf[(size_t)r * N_real + c]) =
                            make_float2(v0, v1);
                    } else {
                        unsigned hi, lo;
                        split2(v0, v1, hi, lo);
                        const size_t o = (size_t)r * (N_real >> 1) + (c >> 1);
                        C0[o] = hi;
                        C1[o] = lo;
                    }
                }
            }
        }
    }
}

// =============================== launch =====================================
extern "C" void kernel_launch(void* const* d_in, const int* in_sizes, int n_in,
                              void* d_out, int out_size)
{
    const float* x  = (const float*)d_in[0];
    const unsigned int* ei = (const unsigned int*)d_in[1];
    const float* W1 = (const float*)d_in[2];
    const float* b1 = (const float*)d_in[3];
    const float* W2 = (const float*)d_in[4];
    const float* b2 = (const float*)d_in[5];
    const float* W3 = (const float*)d_in[6];
    const float* b3 = (const float*)d_in[7];
    const float* W4 = (const float*)d_in[8];
    const float* b4 = (const float*)d_in[9];
    const float* Wl = (const float*)d_in[10];
    const float* bl = (const float*)d_in[11];
    float* out = (float*)d_out;

    const int M = in_sizes[0] / 128;   // 50000
    const int E = in_sizes[1] / 2;     // 800000
    const dim3 blk(256);
    const int nB   = (M + 255) / 256;  // 196 (covers i==N too)
    const int eB   = (E + 255) / 256;
    const int aggB = (M * 32 + 255) / 256;
    const int mT4  = (M + 127) / 128;  // 391
    const int mT3  = (M + 95) / 96;    // 521

    // stage sizes: MT=4 -> 9472 u32, MT=3 -> 8192 u32; two stages each
    const int SMB4 = 2 * 9472 * 4;     // 75776 B
    const int SMB3 = 2 * 8192 * 4;     // 65536 B
    cudaFuncSetAttribute(gemm_bf16<true , 0, 4, 3>, cudaFuncAttributeMaxDynamicSharedMemorySize, SMB3);
    cudaFuncSetAttribute(gemm_bf16<true , 1, 4, 3>, cudaFuncAttributeMaxDynamicSharedMemorySize, SMB3);
    cudaFuncSetAttribute(gemm_bf16<true , 0, 4, 4>, cudaFuncAttributeMaxDynamicSharedMemorySize, SMB4);
    cudaFuncSetAttribute(gemm_bf16<false, 2, 2, 3>, cudaFuncAttributeMaxDynamicSharedMemorySize, SMB3);

    // ---- fused setup: weights + deg zero + scan reset; convert+hist; scan ----
    prep_all    <<<(81920 + 255) / 256, blk>>>(W1, W2, W3, W4, Wl, M);
    convert_hist<<<eB, blk>>>(ei, E, M);
    scan_fused  <<<nB, blk>>>(M, E, nB);
    fill_csr    <<<eB, blk>>>(E);

    // ---- layer 1 (128 -> 128 -> 128), 96-row tiles ----
    gin_aggregate_split<<<aggB, blk>>>(x, 1, M);                         // x -> P
    gemm_bf16<true , 0, 4, 3><<<dim3(1, mT3), blk, SMB3>>>(0, 1, nullptr, b1, OFF_W1, M, 128, 128, 128); // P -> Q
    gemm_bf16<true , 1, 4, 3><<<dim3(1, mT3), blk, SMB3>>>(1, 0, nullptr, b2, OFF_W2, M, 128, 128, 128); // Q -> g_hf

    // ---- layer 2 (128 -> 256 -> 256), 128-row tiles ----
    gin_aggregate_split<<<aggB, blk>>>(nullptr, 0, M);                   // g_hf -> P
    gemm_bf16<true , 0, 4, 4><<<dim3(2, mT4), blk, SMB4>>>(0, 1, nullptr, b3, OFF_W3, M, 256, 256, 128); // P -> Q
    gemm_bf16<true , 0, 4, 4><<<dim3(2, mT4), blk, SMB4>>>(1, 0, nullptr, b4, OFF_W4, M, 256, 256, 256); // Q -> P

    // ---- head (256 -> 40, 96-row x 64-col tiles) ----
    gemm_bf16<false, 2, 2, 3><<<dim3(1, mT3), blk, SMB3>>>(0, 0, out, bl, OFF_WL, M, 40, 128, 256);      // P -> out
}